// round 4
// baseline (speedup 1.0000x reference)
#include <cuda_runtime.h>
#include <math.h>

#define Bn 8
#define NP 511
#define MP 510
#define IMG 512
#define HW2 (NP*NP)      // 261121
#define MP2 (MP*MP)      // 260100
#define IMG2 (IMG*IMG)   // 262144

// ------------------- scratch (__device__ globals; no allocation) -------------------
__device__ float d_Sf[NP*MP];        // forward sine basis 511x510
__device__ float d_Cb[MP*NP];        // inverse cos basis 510x511
__device__ float d_Sb[MP*NP];        // inverse sin basis 510x511
__device__ float d_st[5L*Bn*MP2];    // sw,se,sn,ss,sc
__device__ float d_g1[Bn*MP2];       // mask/coef
__device__ float d_g2[Bn*MP2];       // coef*(1-mask)
__device__ float d_xA[Bn*IMG2];
__device__ float d_xB[Bn*IMG2];
__device__ float d_r1[Bn*MP2];
__device__ float d_T1[Bn*NP*MP];
__device__ float d_Y [Bn*HW2];
__device__ float d_bAr[Bn*4*HW2];
__device__ float d_bAi[Bn*4*HW2];
__device__ float d_bBr[Bn*4*HW2];
__device__ float d_bBi[Bn*4*HW2];
__device__ float d_Zr[Bn*HW2];
__device__ float d_Zi[Bn*HW2];
__device__ float d_P [Bn*MP*NP];
__device__ float d_Q [Bn*MP*NP];
__device__ float d_E [Bn*MP2];
__device__ float d_acc[2];

// ------------------- basis init (exact integer mod reduction) -------------------
__global__ void init_basis_k()
{
    int t = blockIdx.x*256 + threadIdx.x;
    if (t == 0) { d_acc[0] = 0.f; d_acc[1] = 0.f; }
    if (t >= NP*NP) return;
    int p = t / NP;      // 0..510
    int q = t % NP;      // 0..510
    // forward: S_f[p][m], m = q in [0,510)
    if (q < MP) {
        int I = (q+1)*(p-255);
        int r = I % 1022;                 // |r| < 1022
        d_Sf[p*MP + q] = sinpif((float)r / 511.0f);
    }
    // inverse: Cb/Sb[m][j], m = p in [0,510), j = q in [0,511)
    if (p < MP) {
        int I = p*(q-255);
        int r = I % 1022;
        float a = (float)r / 511.0f;
        d_Cb[p*NP + q] = cospif(a);
        d_Sb[p*NP + q] = sinpif(a);
    }
}

// ------------------- stencil + masks -------------------
__global__ void stencil_k(const float* __restrict__ coef)
{
    long t = blockIdx.x*256L + threadIdx.x;
    if (t >= (long)Bn*MP2) return;
    int b = (int)(t / MP2);
    int p = (int)(t % MP2);
    int i = p / MP, j = p % MP;
    const float* cb = coef + (long)b*MP2;
    float a   = cb[p];
    float aw  = cb[i*MP + (j>0    ? j-1 : 0)];
    float ae  = cb[i*MP + (j<MP-1 ? j+1 : MP-1)];
    float an  = cb[(i<MP-1 ? i+1 : MP-1)*MP + j];
    float as_ = cb[(i>0    ? i-1 : 0)*MP + j];
    float sw = -2.f*aw *a/(aw +a);
    float se = -2.f*ae *a/(ae +a);
    float sn = -2.f*an *a/(an +a);
    float ss = -2.f*as_*a/(as_+a);
    d_st[0L*Bn*MP2 + t] = sw;
    d_st[1L*Bn*MP2 + t] = se;
    d_st[2L*Bn*MP2 + t] = sn;
    d_st[3L*Bn*MP2 + t] = ss;
    d_st[4L*Bn*MP2 + t] = -(sw+se+sn+ss);
    float m = (a < 1.0f) ? 1.0f : 0.0f;
    d_g1[t] = m / a;
    d_g2[t] = a * (1.0f - m);
}

__global__ void zero_k(float* __restrict__ p, long n)
{
    long t = blockIdx.x*256L + threadIdx.x;
    if (t < n) p[t] = 0.f;
}

// ------------------- smoothing: x_new = x + w*(f - A(x)) -------------------
__global__ void smooth_k(const float* __restrict__ xin, float* __restrict__ xout,
                         const float* __restrict__ f)
{
    long t = blockIdx.x*256L + threadIdx.x;
    if (t >= (long)Bn*IMG2) return;
    int b = (int)(t / IMG2);
    int p = (int)(t % IMG2);
    int i = p / IMG, j = p % IMG;
    const float w = 40.0f/512.0f;
    float xv = xin[t];
    float fv = f[t];
    if (i==0 || i==IMG-1 || j==0 || j==IMG-1) { xout[t] = xv + w*fv; return; }
    long sb = (long)b*MP2 + (long)(i-1)*MP + (j-1);
    float sw = d_st[0L*Bn*MP2 + sb];
    float se = d_st[1L*Bn*MP2 + sb];
    float sn = d_st[2L*Bn*MP2 + sb];
    float ss = d_st[3L*Bn*MP2 + sb];
    float sc = d_st[4L*Bn*MP2 + sb];
    const float* xb = xin + (long)b*IMG2;
    float Ax = ss*xb[(i-1)*IMG + j] + sw*xb[i*IMG + j-1] + sc*xv
             + se*xb[i*IMG + j+1] + sn*xb[(i+1)*IMG + j];
    xout[t] = xv + w*(fv - Ax);
}

// ------------------- interior residual r1 = (f - A(x))[1:-1,1:-1] -------------------
__global__ void resid1_k(const float* __restrict__ x, const float* __restrict__ f)
{
    long t = blockIdx.x*256L + threadIdx.x;
    if (t >= (long)Bn*MP2) return;
    int b = (int)(t / MP2);
    int p = (int)(t % MP2);
    int i = p / MP + 1, j = p % MP + 1;
    float sw = d_st[0L*Bn*MP2 + t];
    float se = d_st[1L*Bn*MP2 + t];
    float sn = d_st[2L*Bn*MP2 + t];
    float ss = d_st[3L*Bn*MP2 + t];
    float sc = d_st[4L*Bn*MP2 + t];
    const float* xb = x + (long)b*IMG2;
    float Ax = ss*xb[(i-1)*IMG + j] + sw*xb[i*IMG + j-1] + sc*xb[i*IMG + j]
             + se*xb[i*IMG + j+1] + sn*xb[(i+1)*IMG + j];
    d_r1[t] = f[(long)b*IMG2 + i*IMG + j] - Ax;
}

// ------------------- batched SGEMM: D = alpha*op(A)*op(B) + beta*D -------------------
template<int TA, int TB>
__global__ void sgemm_k(const float* __restrict__ A, int lda, long sA,
                        const float* __restrict__ B, int ldb, long sB,
                        float* __restrict__ D, int ldc, long sD,
                        int M, int N, int K, float alpha, float beta)
{
    __shared__ float As[16][64];
    __shared__ float Bs[16][64];
    int b = blockIdx.z;
    A += (long)b*sA; B += (long)b*sB; D += (long)b*sD;
    int m0 = blockIdx.y*64, n0 = blockIdx.x*64;
    int tx = threadIdx.x, ty = threadIdx.y;
    int tid = ty*16 + tx;
    float acc[4][4];
    #pragma unroll
    for (int i=0;i<4;i++)
        #pragma unroll
        for (int j=0;j<4;j++) acc[i][j] = 0.f;

    for (int k0 = 0; k0 < K; k0 += 16) {
        #pragma unroll
        for (int e = tid; e < 1024; e += 256) {
            int mm, kk;
            if (TA) { mm = e & 63; kk = e >> 6; }
            else    { kk = e & 15; mm = e >> 4; }
            int m = m0 + mm, k = k0 + kk;
            float v = 0.f;
            if (m < M && k < K) v = TA ? A[(long)k*lda + m] : A[(long)m*lda + k];
            As[kk][mm] = v;
        }
        #pragma unroll
        for (int e = tid; e < 1024; e += 256) {
            int nn, kk;
            if (TB) { kk = e & 15; nn = e >> 4; }
            else    { nn = e & 63; kk = e >> 6; }
            int n = n0 + nn, k = k0 + kk;
            float v = 0.f;
            if (n < N && k < K) v = TB ? B[(long)n*ldb + k] : B[(long)k*ldb + n];
            Bs[kk][nn] = v;
        }
        __syncthreads();
        #pragma unroll
        for (int kk=0; kk<16; kk++) {
            float4 a4 = *reinterpret_cast<const float4*>(&As[kk][ty*4]);
            float4 b4 = *reinterpret_cast<const float4*>(&Bs[kk][tx*4]);
            float a[4] = {a4.x,a4.y,a4.z,a4.w};
            float bb[4] = {b4.x,b4.y,b4.z,b4.w};
            #pragma unroll
            for (int i=0;i<4;i++)
                #pragma unroll
                for (int j=0;j<4;j++) acc[i][j] += a[i]*bb[j];
        }
        __syncthreads();
    }
    #pragma unroll
    for (int i=0;i<4;i++) {
        int m = m0 + ty*4 + i;
        if (m >= M) continue;
        #pragma unroll
        for (int j=0;j<4;j++) {
            int n = n0 + tx*4 + j;
            if (n >= N) continue;
            long idx = (long)m*ldc + n;
            float v = alpha*acc[i][j];
            if (beta != 0.f) v += beta*D[idx];
            D[idx] = v;
        }
    }
}

// ------------------- complex 3x3 conv (pad 1), per-batch weights, opt theta fuse ----
__global__ void conv_k(const float* __restrict__ inR, const float* __restrict__ inI,
                       long inBS,
                       float* __restrict__ outR, float* __restrict__ outI, long outBS,
                       const float* __restrict__ wR, const float* __restrict__ wI,
                       int Cin, int Cout, int trans,
                       const float* __restrict__ thR, const float* __restrict__ thI)
{
    __shared__ float sR[4][10][34];
    __shared__ float sI[4][10][34];
    __shared__ float swr[4][4][9];
    __shared__ float swi[4][4][9];
    int b = blockIdx.z;
    int bx = blockIdx.x*32, by = blockIdx.y*8;
    int tid = threadIdx.y*32 + threadIdx.x;

    for (int e = tid; e < Cout*Cin*9; e += 256) {
        int co = e / (Cin*9);
        int rem = e % (Cin*9);
        int ci = rem / 9;
        int k  = rem % 9;
        int ky = k/3, kx = k%3;
        int src; float sgn;
        if (!trans) { src = ((b*Cout + co)*Cin + ci)*9 + ky*3 + kx; sgn =  1.f; }
        else        { src = ((b*Cin  + ci)*Cout + co)*9 + kx*3 + ky; sgn = -1.f; }
        swr[co][ci][k] = wR[src];
        swi[co][ci][k] = sgn * wI[src];
    }
    for (int c = 0; c < Cin; c++) {
        for (int e = tid; e < 340; e += 256) {
            int ly = e / 34, lx = e % 34;
            int gy = by + ly - 1, gx = bx + lx - 1;
            bool ok = (gy >= 0 && gy < NP && gx >= 0 && gx < NP);
            float vr = 0.f, vi = 0.f;
            if (ok) {
                long idx = (long)b*inBS + (long)c*HW2 + (long)gy*NP + gx;
                vr = inR[idx];
                if (inI) vi = inI[idx];
            }
            sR[c][ly][lx] = vr;
            sI[c][ly][lx] = vi;
        }
    }
    __syncthreads();
    int ox = bx + threadIdx.x, oy = by + threadIdx.y;
    if (ox >= NP || oy >= NP) return;
    float tr = 1.f, ti = 0.f;
    if (thR) {
        long tp = (long)b*HW2 + (long)oy*NP + ox;
        tr = thR[tp]; ti = thI[tp];
    }
    for (int co = 0; co < Cout; co++) {
        float ar = 0.f, ai = 0.f;
        for (int ci = 0; ci < Cin; ci++) {
            #pragma unroll
            for (int k = 0; k < 9; k++) {
                int ky = k/3, kx = k%3;
                float xr = sR[ci][threadIdx.y+ky][threadIdx.x+kx];
                float xi = sI[ci][threadIdx.y+ky][threadIdx.x+kx];
                float wr = swr[co][ci][k], wi2 = swi[co][ci][k];
                ar += xr*wr - xi*wi2;
                ai += xr*wi2 + xi*wr;
            }
        }
        long op = (long)b*outBS + (long)co*HW2 + (long)oy*NP + ox;
        if (thR) {
            float nr = ar*tr - ai*ti;
            float ni = ar*ti + ai*tr;
            outR[op] = nr; outI[op] = ni;
        } else {
            outR[op] = ar; outI[op] = ai;
        }
    }
}

// ------------------- apply correction: x[interior] += E*g -------------------
__global__ void apply_k(const float* __restrict__ E, const float* __restrict__ g)
{
    long t = blockIdx.x*256L + threadIdx.x;
    if (t >= (long)Bn*MP2) return;
    int b = (int)(t / MP2);
    int p = (int)(t % MP2);
    int i = p / MP + 1, j = p % MP + 1;
    d_xA[(long)b*IMG2 + (long)i*IMG + j] += E[t]*g[t];
}

// ------------------- final reduction: sum r^2 and f^2 -------------------
__global__ void reduce_k(const float* __restrict__ f, const float* __restrict__ x)
{
    __shared__ float sr[256];
    __shared__ float sf[256];
    long t = blockIdx.x*256L + threadIdx.x;
    float rv = 0.f, fv = 0.f;
    if (t < (long)Bn*IMG2) {
        int b = (int)(t / IMG2);
        int p = (int)(t % IMG2);
        int i = p / IMG, j = p % IMG;
        fv = f[t];
        float Ax = 0.f;
        if (!(i==0 || i==IMG-1 || j==0 || j==IMG-1)) {
            long sb = (long)b*MP2 + (long)(i-1)*MP + (j-1);
            float sw = d_st[0L*Bn*MP2 + sb];
            float se = d_st[1L*Bn*MP2 + sb];
            float sn = d_st[2L*Bn*MP2 + sb];
            float ss = d_st[3L*Bn*MP2 + sb];
            float sc = d_st[4L*Bn*MP2 + sb];
            const float* xb = x + (long)b*IMG2;
            Ax = ss*xb[(i-1)*IMG + j] + sw*xb[i*IMG + j-1] + sc*xb[i*IMG + j]
               + se*xb[i*IMG + j+1] + sn*xb[(i+1)*IMG + j];
        }
        rv = fv - Ax;
    }
    sr[threadIdx.x] = rv*rv;
    sf[threadIdx.x] = fv*fv;
    __syncthreads();
    for (int s = 128; s > 0; s >>= 1) {
        if (threadIdx.x < s) { sr[threadIdx.x] += sr[threadIdx.x+s]; sf[threadIdx.x] += sf[threadIdx.x+s]; }
        __syncthreads();
    }
    if (threadIdx.x == 0) {
        atomicAdd(&d_acc[0], sr[0]);
        atomicAdd(&d_acc[1], sf[0]);
    }
}

__global__ void finalize_k(float* __restrict__ out)
{
    out[0] = sqrtf(d_acc[0] / d_acc[1]);
}

// ------------------- host side -------------------
static void launch_gemm(bool tb, int M, int N, int K, float alpha,
                        const float* A, int lda, long sA,
                        const float* B, int ldb, long sB,
                        float* D, int ldc, long sD, float beta)
{
    dim3 blk(16,16), grd((N+63)/64, (M+63)/64, Bn);
    if (tb) sgemm_k<0,1><<<grd,blk>>>(A,lda,sA,B,ldb,sB,D,ldc,sD,M,N,K,alpha,beta);
    else    sgemm_k<0,0><<<grd,blk>>>(A,lda,sA,B,ldb,sB,D,ldc,sD,M,N,K,alpha,beta);
}

extern "C" void kernel_launch(void* const* d_in, const int* in_sizes, int n_in,
                              void* d_out, int out_size)
{
    (void)in_sizes; (void)n_in; (void)out_size;
    const float* f    = (const float*)d_in[0];
    const float* coef = (const float*)d_in[1];
    // weights, ordered: [h][layer][r/i]
    const float* W[2][3][2] = {
        { { (const float*)d_in[2],  (const float*)d_in[3]  },
          { (const float*)d_in[4],  (const float*)d_in[5]  },
          { (const float*)d_in[6],  (const float*)d_in[7]  } },
        { { (const float*)d_in[10], (const float*)d_in[11] },
          { (const float*)d_in[12], (const float*)d_in[13] },
          { (const float*)d_in[14], (const float*)d_in[15] } }
    };
    const float* TH[2][2] = {
        { (const float*)d_in[8],  (const float*)d_in[9]  },
        { (const float*)d_in[16], (const float*)d_in[17] }
    };

    float *pSf, *pCb, *pSb, *pxA, *pxB, *pr1, *pT1, *pY;
    float *pbAr, *pbAi, *pbBr, *pbBi, *pZr, *pZi, *pP, *pQ, *pE, *pg1, *pg2;
    cudaGetSymbolAddress((void**)&pSf, d_Sf);
    cudaGetSymbolAddress((void**)&pCb, d_Cb);
    cudaGetSymbolAddress((void**)&pSb, d_Sb);
    cudaGetSymbolAddress((void**)&pxA, d_xA);
    cudaGetSymbolAddress((void**)&pxB, d_xB);
    cudaGetSymbolAddress((void**)&pr1, d_r1);
    cudaGetSymbolAddress((void**)&pT1, d_T1);
    cudaGetSymbolAddress((void**)&pY,  d_Y);
    cudaGetSymbolAddress((void**)&pbAr, d_bAr);
    cudaGetSymbolAddress((void**)&pbAi, d_bAi);
    cudaGetSymbolAddress((void**)&pbBr, d_bBr);
    cudaGetSymbolAddress((void**)&pbBi, d_bBi);
    cudaGetSymbolAddress((void**)&pZr, d_Zr);
    cudaGetSymbolAddress((void**)&pZi, d_Zi);
    cudaGetSymbolAddress((void**)&pP,  d_P);
    cudaGetSymbolAddress((void**)&pQ,  d_Q);
    cudaGetSymbolAddress((void**)&pE,  d_E);
    cudaGetSymbolAddress((void**)&pg1, d_g1);
    cudaGetSymbolAddress((void**)&pg2, d_g2);

    const int EW_IMG = (Bn*IMG2 + 255)/256;   // 8192
    const int EW_MP  = (Bn*MP2  + 255)/256;   // 8129
    const int EW_NP  = (NP*NP   + 255)/256;   // 1021

    init_basis_k<<<EW_NP,256>>>();
    stencil_k<<<EW_MP,256>>>(coef);
    zero_k<<<EW_IMG,256>>>(pxA, (long)Bn*IMG2);

    const int KITER = 1;   // epoch = 1 always in this dataset -> K = 1
    for (int kk = 0; kk < KITER; kk++) {
        // 10 smoothing sweeps, ping-pong; ends with x in d_xA
        float* cur = pxA; float* nxt = pxB;
        for (int t = 0; t < 10; t++) {
            smooth_k<<<EW_IMG,256>>>(cur, nxt, f);
            float* tmp = cur; cur = nxt; nxt = tmp;
        }
        // residual on interior
        resid1_k<<<EW_MP,256>>>(pxA, f);

        // forward sine transform: Y = -(1/511^2) * Sf * r1 * Sf^T  (shared by both H)
        launch_gemm(false, NP, MP, MP, 1.0f,
                    pSf, MP, 0,  pr1, MP, (long)MP2,  pT1, MP, (long)NP*MP, 0.f);
        launch_gemm(true,  NP, NP, MP, -1.0f/(511.0f*511.0f),
                    pT1, MP, (long)NP*MP,  pSf, MP, 0,  pY, NP, (long)HW2, 0.f);

        dim3 cblk(32,8), cgrd((NP+31)/32, (NP+7)/8, Bn);
        for (int h = 0; h < 2; h++) {
            // forward conv chain: Y(1ch real) -> 4 -> 4 -> 1 (theta fused at layer 3)
            conv_k<<<cgrd,cblk>>>(pY, nullptr, (long)HW2,
                                  pbAr, pbAi, 4L*HW2,
                                  W[h][0][0], W[h][0][1], 1, 4, 0, nullptr, nullptr);
            conv_k<<<cgrd,cblk>>>(pbAr, pbAi, 4L*HW2,
                                  pbBr, pbBi, 4L*HW2,
                                  W[h][1][0], W[h][1][1], 4, 4, 0, nullptr, nullptr);
            conv_k<<<cgrd,cblk>>>(pbBr, pbBi, 4L*HW2,
                                  pZr, pZi, (long)HW2,
                                  W[h][2][0], W[h][2][1], 4, 1, 0, TH[h][0], TH[h][1]);
            // backward conj-transposed chain: 1 -> 4 -> 4 -> 1
            conv_k<<<cgrd,cblk>>>(pZr, pZi, (long)HW2,
                                  pbBr, pbBi, 4L*HW2,
                                  W[h][2][0], W[h][2][1], 1, 4, 1, nullptr, nullptr);
            conv_k<<<cgrd,cblk>>>(pbBr, pbBi, 4L*HW2,
                                  pbAr, pbAi, 4L*HW2,
                                  W[h][1][0], W[h][1][1], 4, 4, 1, nullptr, nullptr);
            conv_k<<<cgrd,cblk>>>(pbAr, pbAi, 4L*HW2,
                                  pZr, pZi, (long)HW2,
                                  W[h][0][0], W[h][0][1], 4, 1, 1, nullptr, nullptr);

            // inverse transform: E = (C Zr + S Zi) C^T + (C Zi - S Zr) S^T
            launch_gemm(false, MP, NP, NP,  1.0f,
                        pCb, NP, 0,  pZr, NP, (long)HW2,  pP, NP, (long)MP*NP, 0.f);
            launch_gemm(false, MP, NP, NP,  1.0f,
                        pSb, NP, 0,  pZi, NP, (long)HW2,  pP, NP, (long)MP*NP, 1.f);
            launch_gemm(false, MP, NP, NP,  1.0f,
                        pCb, NP, 0,  pZi, NP, (long)HW2,  pQ, NP, (long)MP*NP, 0.f);
            launch_gemm(false, MP, NP, NP, -1.0f,
                        pSb, NP, 0,  pZr, NP, (long)HW2,  pQ, NP, (long)MP*NP, 1.f);
            launch_gemm(true,  MP, MP, NP,  1.0f,
                        pP, NP, (long)MP*NP,  pCb, NP, 0,  pE, MP, (long)MP2, 0.f);
            launch_gemm(true,  MP, MP, NP,  1.0f,
                        pQ, NP, (long)MP*NP,  pSb, NP, 0,  pE, MP, (long)MP2, 1.f);

            apply_k<<<EW_MP,256>>>(pE, h == 0 ? pg1 : pg2);
        }
    }

    reduce_k<<<EW_IMG,256>>>(f, pxA);
    finalize_k<<<1,1>>>((float*)d_out);
}

// round 12
// speedup vs baseline: 1.8030x; 1.8030x over previous
#include <cuda_runtime.h>
#include <math.h>

#define Bn 8
#define NP 511
#define MP 510
#define IMG 512
#define LD  512                 // padded row stride for all matrices
#define HW2 (NP*NP)
#define MP2 (MP*MP)
#define IMG2 (IMG*IMG)
#define CST ((long)NP*LD)       // channel stride for conv buffers

// ------------------- scratch (__device__ globals; no allocation) -------------------
__device__ __align__(16) float d_Sf [NP*LD];   // Sf[p][m]  p<511, m<510
__device__ __align__(16) float d_SfT[MP*LD];   // SfT[m][p] = Sf[p][m]
__device__ __align__(16) float d_Cb [MP*LD];   // Cb[m][j]  m<510, j<511
__device__ __align__(16) float d_Sb [MP*LD];
__device__ __align__(16) float d_CbT[NP*LD];   // CbT[j][m] = Cb[m][j]
__device__ __align__(16) float d_SbT[NP*LD];
__device__ __align__(16) float d_st[5L*Bn*MP2];
__device__ __align__(16) float d_g1[Bn*MP2];
__device__ __align__(16) float d_g2[Bn*MP2];
__device__ __align__(16) float d_xA[Bn*IMG2];
__device__ __align__(16) float d_xB[Bn*IMG2];
__device__ __align__(16) float d_r1[(long)Bn*MP*LD];
__device__ __align__(16) float d_T1[(long)Bn*NP*LD];
__device__ __align__(16) float d_Y [(long)Bn*NP*LD];
__device__ __align__(16) float d_bAr[(long)Bn*4*NP*LD];
__device__ __align__(16) float d_bAi[(long)Bn*4*NP*LD];
__device__ __align__(16) float d_bBr[(long)Bn*4*NP*LD];
__device__ __align__(16) float d_bBi[(long)Bn*4*NP*LD];
__device__ __align__(16) float d_Zr[(long)Bn*NP*LD];
__device__ __align__(16) float d_Zi[(long)Bn*NP*LD];
__device__ __align__(16) float d_P [(long)Bn*MP*LD];
__device__ __align__(16) float d_Q [(long)Bn*MP*LD];
__device__ float d_acc[2];

// ------------------- basis init (exact integer mod reduction) -------------------
__global__ void init_basis_k()
{
    int t = blockIdx.x*256 + threadIdx.x;
    if (t == 0) { d_acc[0] = 0.f; d_acc[1] = 0.f; }
    if (t >= NP*NP) return;
    int p = t / NP;   // 0..510
    int q = t % NP;   // 0..510
    if (q < MP) {
        int r = ((q+1)*(p-255)) % 1022;
        float v = sinpif((float)r / 511.0f);
        d_Sf [p*LD + q] = v;    // Sf[p][q]
        d_SfT[q*LD + p] = v;    // SfT[q][p]
    }
    if (p < MP) {
        int r = (p*(q-255)) % 1022;
        float a = (float)r / 511.0f;
        float c = cospif(a), s = sinpif(a);
        d_Cb [p*LD + q] = c;
        d_Sb [p*LD + q] = s;
        d_CbT[q*LD + p] = c;
        d_SbT[q*LD + p] = s;
    }
}

// ------------------- stencil + masks -------------------
__global__ void stencil_k(const float* __restrict__ coef)
{
    long t = blockIdx.x*256L + threadIdx.x;
    if (t >= (long)Bn*MP2) return;
    int b = (int)(t / MP2);
    int p = (int)(t % MP2);
    int i = p / MP, j = p % MP;
    const float* cb = coef + (long)b*MP2;
    float a   = cb[p];
    float aw  = cb[i*MP + (j>0    ? j-1 : 0)];
    float ae  = cb[i*MP + (j<MP-1 ? j+1 : MP-1)];
    float an  = cb[(i<MP-1 ? i+1 : MP-1)*MP + j];
    float as_ = cb[(i>0    ? i-1 : 0)*MP + j];
    float sw = -2.f*aw *a/(aw +a);
    float se = -2.f*ae *a/(ae +a);
    float sn = -2.f*an *a/(an +a);
    float ss = -2.f*as_*a/(as_+a);
    d_st[0L*Bn*MP2 + t] = sw;
    d_st[1L*Bn*MP2 + t] = se;
    d_st[2L*Bn*MP2 + t] = sn;
    d_st[3L*Bn*MP2 + t] = ss;
    d_st[4L*Bn*MP2 + t] = -(sw+se+sn+ss);
    float m = (a < 1.0f) ? 1.0f : 0.0f;
    d_g1[t] = m / a;
    d_g2[t] = a * (1.0f - m);
}

__global__ void zero_k(float* __restrict__ p, long n)
{
    long t = blockIdx.x*256L + threadIdx.x;
    if (t < n) p[t] = 0.f;
}

// ------------------- smoothing: x_new = x + w*(f - A(x)) -------------------
__global__ void smooth_k(const float* __restrict__ xin, float* __restrict__ xout,
                         const float* __restrict__ f)
{
    long t = blockIdx.x*256L + threadIdx.x;
    if (t >= (long)Bn*IMG2) return;
    int b = (int)(t / IMG2);
    int p = (int)(t % IMG2);
    int i = p / IMG, j = p % IMG;
    const float w = 40.0f/512.0f;
    float xv = xin[t];
    float fv = f[t];
    if (i==0 || i==IMG-1 || j==0 || j==IMG-1) { xout[t] = xv + w*fv; return; }
    long sb = (long)b*MP2 + (long)(i-1)*MP + (j-1);
    float sw = d_st[0L*Bn*MP2 + sb];
    float se = d_st[1L*Bn*MP2 + sb];
    float sn = d_st[2L*Bn*MP2 + sb];
    float ss = d_st[3L*Bn*MP2 + sb];
    float sc = d_st[4L*Bn*MP2 + sb];
    const float* xb = xin + (long)b*IMG2;
    float Ax = ss*xb[(i-1)*IMG + j] + sw*xb[i*IMG + j-1] + sc*xv
             + se*xb[i*IMG + j+1] + sn*xb[(i+1)*IMG + j];
    xout[t] = xv + w*(fv - Ax);
}

// ------------------- interior residual r1 (padded LD rows) -------------------
__global__ void resid1_k(const float* __restrict__ x, const float* __restrict__ f)
{
    long t = blockIdx.x*256L + threadIdx.x;
    if (t >= (long)Bn*MP2) return;
    int b = (int)(t / MP2);
    int p = (int)(t % MP2);
    int i = p / MP + 1, j = p % MP + 1;
    float sw = d_st[0L*Bn*MP2 + t];
    float se = d_st[1L*Bn*MP2 + t];
    float sn = d_st[2L*Bn*MP2 + t];
    float ss = d_st[3L*Bn*MP2 + t];
    float sc = d_st[4L*Bn*MP2 + t];
    const float* xb = x + (long)b*IMG2;
    float Ax = ss*xb[(i-1)*IMG + j] + sw*xb[i*IMG + j-1] + sc*xb[i*IMG + j]
             + se*xb[i*IMG + j+1] + sn*xb[(i+1)*IMG + j];
    d_r1[(long)b*MP*LD + (long)(i-1)*LD + (j-1)] = f[(long)b*IMG2 + i*IMG + j] - Ax;
}

// ------------------- plain GEMM: D = alpha * A(row-major) * B(row-major) ----------
// All row strides = LD(512). 128x64 tile, 8x4 microtile, 256 threads.
__global__ __launch_bounds__(256) void gemmNN_k(
    const float* __restrict__ A, long sA,
    const float* __restrict__ B, long sB,
    float* __restrict__ D, long sD,
    int M, int N, int K, float alpha)
{
    __shared__ float As[128][16];
    __shared__ float Bs[16][64];
    int b = blockIdx.z;
    A += (long)b*sA; B += (long)b*sB; D += (long)b*sD;
    int m0 = blockIdx.y*128, n0 = blockIdx.x*64;
    int tid = threadIdx.x;
    int tx = tid & 15, ty = tid >> 4;
    float acc[8][4];
    #pragma unroll
    for (int i=0;i<8;i++)
        #pragma unroll
        for (int j=0;j<4;j++) acc[i][j]=0.f;

    for (int k0 = 0; k0 < K; k0 += 16) {
        #pragma unroll
        for (int u = 0; u < 2; u++) {
            int e = tid + u*256;
            int mm = e >> 2, kg = (e & 3) << 2;
            int m = m0 + mm, k = k0 + kg;
            float4 v = make_float4(0.f,0.f,0.f,0.f);
            if (m < M) {
                if (k + 3 < K) v = *(const float4*)(A + (long)m*LD + k);
                else {
                    float* vv = (float*)&v;
                    #pragma unroll
                    for (int q2=0;q2<4;q2++) if (k+q2 < K) vv[q2] = A[(long)m*LD + k + q2];
                }
            }
            *(float4*)&As[mm][kg] = v;
        }
        {
            int nn4 = (tid & 15) << 2, kk = tid >> 4;
            int k = k0 + kk;
            float4 v = make_float4(0.f,0.f,0.f,0.f);
            if (k < K) {
                if (n0 + nn4 + 3 < N) v = *(const float4*)(B + (long)k*LD + n0 + nn4);
                else {
                    float* vv=(float*)&v;
                    #pragma unroll
                    for (int q2=0;q2<4;q2++) if (n0+nn4+q2 < N) vv[q2] = B[(long)k*LD + n0+nn4+q2];
                }
            }
            *(float4*)&Bs[kk][nn4] = v;
        }
        __syncthreads();
        #pragma unroll
        for (int kk = 0; kk < 16; kk++) {
            float bv[4];
            *(float4*)bv = *(const float4*)&Bs[kk][tx<<2];
            #pragma unroll
            for (int i = 0; i < 8; i++) {
                float a0 = As[(ty<<3)+i][kk];
                #pragma unroll
                for (int j = 0; j < 4; j++) acc[i][j] += a0*bv[j];
            }
        }
        __syncthreads();
    }
    #pragma unroll
    for (int i = 0; i < 8; i++) {
        int m = m0 + (ty<<3) + i;
        if (m >= M) continue;
        #pragma unroll
        for (int j = 0; j < 4; j++) {
            int n = n0 + (tx<<2) + j;
            if (n < N) D[(long)m*LD + n] = alpha*acc[i][j];
        }
    }
}

// ------------------- fused dual GEMM: P = A1*B1 + A2*B2 ; Q = A1*B2 - A2*B1 ------
// A1/A2: [M][LD] shared across batch. B1/B2, P/Q: per-batch.
__global__ __launch_bounds__(256) void gemmPQ_k(
    const float* __restrict__ A1, const float* __restrict__ A2,
    const float* __restrict__ B1, const float* __restrict__ B2, long sB,
    float* __restrict__ P, float* __restrict__ Q, long sD,
    int M, int N, int K)
{
    __shared__ float A1s[64][16], A2s[64][16];
    __shared__ float B1s[16][64], B2s[16][64];
    int b = blockIdx.z;
    B1 += (long)b*sB; B2 += (long)b*sB;
    P += (long)b*sD;  Q += (long)b*sD;
    int m0 = blockIdx.y*64, n0 = blockIdx.x*64;
    int tid = threadIdx.x;
    int tx = tid & 15, ty = tid >> 4;
    float aP[4][4], aQ[4][4];
    #pragma unroll
    for (int i=0;i<4;i++)
        #pragma unroll
        for (int j=0;j<4;j++){ aP[i][j]=0.f; aQ[i][j]=0.f; }

    for (int k0 = 0; k0 < K; k0 += 16) {
        {
            int e = tid;
            int mm = e >> 2, kg = (e & 3) << 2;
            int m = m0 + mm, k = k0 + kg;
            float4 v1 = make_float4(0.f,0.f,0.f,0.f), v2 = v1;
            if (m < M) {
                if (k + 3 < K) {
                    v1 = *(const float4*)(A1 + (long)m*LD + k);
                    v2 = *(const float4*)(A2 + (long)m*LD + k);
                } else {
                    float *p1=(float*)&v1, *p2=(float*)&v2;
                    #pragma unroll
                    for (int q2=0;q2<4;q2++) if (k+q2 < K) {
                        p1[q2] = A1[(long)m*LD + k + q2];
                        p2[q2] = A2[(long)m*LD + k + q2];
                    }
                }
            }
            *(float4*)&A1s[mm][kg] = v1;
            *(float4*)&A2s[mm][kg] = v2;
        }
        {
            int nn4 = (tid & 15) << 2, kk = tid >> 4;
            int k = k0 + kk;
            float4 v1 = make_float4(0.f,0.f,0.f,0.f), v2 = v1;
            if (k < K) {
                if (n0 + nn4 + 3 < N) {
                    v1 = *(const float4*)(B1 + (long)k*LD + n0 + nn4);
                    v2 = *(const float4*)(B2 + (long)k*LD + n0 + nn4);
                } else {
                    float *p1=(float*)&v1, *p2=(float*)&v2;
                    #pragma unroll
                    for (int q2=0;q2<4;q2++) if (n0+nn4+q2 < N) {
                        p1[q2] = B1[(long)k*LD + n0+nn4+q2];
                        p2[q2] = B2[(long)k*LD + n0+nn4+q2];
                    }
                }
            }
            *(float4*)&B1s[kk][nn4] = v1;
            *(float4*)&B2s[kk][nn4] = v2;
        }
        __syncthreads();
        #pragma unroll
        for (int kk = 0; kk < 16; kk++) {
            float br[4], bi[4];
            *(float4*)br = *(const float4*)&B1s[kk][tx<<2];
            *(float4*)bi = *(const float4*)&B2s[kk][tx<<2];
            #pragma unroll
            for (int i = 0; i < 4; i++) {
                float a1 = A1s[(ty<<2)+i][kk];
                float a2 = A2s[(ty<<2)+i][kk];
                #pragma unroll
                for (int j = 0; j < 4; j++) {
                    aP[i][j] += a1*br[j] + a2*bi[j];
                    aQ[i][j] += a1*bi[j] - a2*br[j];
                }
            }
        }
        __syncthreads();
    }
    #pragma unroll
    for (int i = 0; i < 4; i++) {
        int m = m0 + (ty<<2) + i;
        if (m >= M) continue;
        #pragma unroll
        for (int j = 0; j < 4; j++) {
            int n = n0 + (tx<<2) + j;
            if (n < N) {
                P[(long)m*LD + n] = aP[i][j];
                Q[(long)m*LD + n] = aQ[i][j];
            }
        }
    }
}

// ------------- fused stage-2 + apply: x[int] += (P*CbT + Q*SbT) .* g --------------
__global__ __launch_bounds__(256) void gemmE_k(
    const float* __restrict__ P, const float* __restrict__ Q, long sA,
    const float* __restrict__ Bc, const float* __restrict__ Bs2,
    const float* __restrict__ g, float* __restrict__ x,
    int M, int N, int K)
{
    __shared__ float Ps[64][16], Qs[64][16];
    __shared__ float Cs[16][64], Ss[16][64];
    int b = blockIdx.z;
    P += (long)b*sA; Q += (long)b*sA;
    g += (long)b*MP2; x += (long)b*IMG2;
    int m0 = blockIdx.y*64, n0 = blockIdx.x*64;
    int tid = threadIdx.x;
    int tx = tid & 15, ty = tid >> 4;
    float acc[4][4];
    #pragma unroll
    for (int i=0;i<4;i++)
        #pragma unroll
        for (int j=0;j<4;j++) acc[i][j]=0.f;

    for (int k0 = 0; k0 < K; k0 += 16) {
        {
            int e = tid;
            int mm = e >> 2, kg = (e & 3) << 2;
            int m = m0 + mm, k = k0 + kg;
            float4 v1 = make_float4(0.f,0.f,0.f,0.f), v2 = v1;
            if (m < M) {
                if (k + 3 < K) {
                    v1 = *(const float4*)(P + (long)m*LD + k);
                    v2 = *(const float4*)(Q + (long)m*LD + k);
                } else {
                    float *p1=(float*)&v1, *p2=(float*)&v2;
                    #pragma unroll
                    for (int q2=0;q2<4;q2++) if (k+q2 < K) {
                        p1[q2] = P[(long)m*LD + k + q2];
                        p2[q2] = Q[(long)m*LD + k + q2];
                    }
                }
            }
            *(float4*)&Ps[mm][kg] = v1;
            *(float4*)&Qs[mm][kg] = v2;
        }
        {
            int nn4 = (tid & 15) << 2, kk = tid >> 4;
            int k = k0 + kk;
            float4 v1 = make_float4(0.f,0.f,0.f,0.f), v2 = v1;
            if (k < K) {
                if (n0 + nn4 + 3 < N) {
                    v1 = *(const float4*)(Bc  + (long)k*LD + n0 + nn4);
                    v2 = *(const float4*)(Bs2 + (long)k*LD + n0 + nn4);
                } else {
                    float *p1=(float*)&v1, *p2=(float*)&v2;
                    #pragma unroll
                    for (int q2=0;q2<4;q2++) if (n0+nn4+q2 < N) {
                        p1[q2] = Bc [(long)k*LD + n0+nn4+q2];
                        p2[q2] = Bs2[(long)k*LD + n0+nn4+q2];
                    }
                }
            }
            *(float4*)&Cs[kk][nn4] = v1;
            *(float4*)&Ss[kk][nn4] = v2;
        }
        __syncthreads();
        #pragma unroll
        for (int kk = 0; kk < 16; kk++) {
            float bc[4], bs[4];
            *(float4*)bc = *(const float4*)&Cs[kk][tx<<2];
            *(float4*)bs = *(const float4*)&Ss[kk][tx<<2];
            #pragma unroll
            for (int i = 0; i < 4; i++) {
                float p0 = Ps[(ty<<2)+i][kk];
                float q0 = Qs[(ty<<2)+i][kk];
                #pragma unroll
                for (int j = 0; j < 4; j++)
                    acc[i][j] += p0*bc[j] + q0*bs[j];
            }
        }
        __syncthreads();
    }
    #pragma unroll
    for (int i = 0; i < 4; i++) {
        int m = m0 + (ty<<2) + i;
        if (m >= M) continue;
        #pragma unroll
        for (int j = 0; j < 4; j++) {
            int n = n0 + (tx<<2) + j;
            if (n < N)
                x[(long)(m+1)*IMG + (n+1)] += acc[i][j]*g[(long)m*MP + n];
        }
    }
}

// ------------------- complex 3x3 conv, ci-outer register window --------------------
template<int CIN, int COUT>
__global__ void conv_k(const float* __restrict__ inR, const float* __restrict__ inI,
                       float* __restrict__ outR, float* __restrict__ outI,
                       const float* __restrict__ wR, const float* __restrict__ wI,
                       int trans,
                       const float* __restrict__ thR, const float* __restrict__ thI)
{
    __shared__ float sR[CIN][10][34];
    __shared__ float sI[CIN][10][34];
    __shared__ float swr[COUT][CIN][9];
    __shared__ float swi[COUT][CIN][9];
    int b = blockIdx.z;
    int bx = blockIdx.x*32, by = blockIdx.y*8;
    int tid = threadIdx.y*32 + threadIdx.x;

    for (int e = tid; e < COUT*CIN*9; e += 256) {
        int co = e / (CIN*9);
        int rem = e % (CIN*9);
        int ci = rem / 9;
        int k  = rem % 9;
        int ky = k/3, kx = k%3;
        int src; float sgn;
        if (!trans) { src = ((b*COUT + co)*CIN + ci)*9 + ky*3 + kx; sgn =  1.f; }
        else        { src = ((b*CIN  + ci)*COUT + co)*9 + kx*3 + ky; sgn = -1.f; }
        swr[co][ci][k] = wR[src];
        swi[co][ci][k] = sgn * wI[src];
    }
    #pragma unroll
    for (int c = 0; c < CIN; c++) {
        for (int e = tid; e < 340; e += 256) {
            int ly = e / 34, lx = e % 34;
            int gy = by + ly - 1, gx = bx + lx - 1;
            bool ok = (gy >= 0 && gy < NP && gx >= 0 && gx < NP);
            float vr = 0.f, vi = 0.f;
            if (ok) {
                long idx = (long)b*CIN*CST + (long)c*CST + (long)gy*LD + gx;
                vr = inR[idx];
                if (inI) vi = inI[idx];
            }
            sR[c][ly][lx] = vr;
            sI[c][ly][lx] = vi;
        }
    }
    __syncthreads();
    int ox = bx + threadIdx.x, oy = by + threadIdx.y;
    if (ox >= NP || oy >= NP) return;

    float ar[COUT], ai[COUT];
    #pragma unroll
    for (int co = 0; co < COUT; co++) { ar[co]=0.f; ai[co]=0.f; }

    #pragma unroll
    for (int ci = 0; ci < CIN; ci++) {
        float xr[9], xi[9];
        #pragma unroll
        for (int ky = 0; ky < 3; ky++)
            #pragma unroll
            for (int kx = 0; kx < 3; kx++) {
                xr[ky*3+kx] = sR[ci][threadIdx.y+ky][threadIdx.x+kx];
                xi[ky*3+kx] = sI[ci][threadIdx.y+ky][threadIdx.x+kx];
            }
        #pragma unroll
        for (int co = 0; co < COUT; co++) {
            #pragma unroll
            for (int k = 0; k < 9; k++) {
                float wr = swr[co][ci][k], wi2 = swi[co][ci][k];
                ar[co] += xr[k]*wr - xi[k]*wi2;
                ai[co] += xr[k]*wi2 + xi[k]*wr;
            }
        }
    }

    float tr = 1.f, ti = 0.f;
    if (thR) {
        long tp = (long)b*HW2 + (long)oy*NP + ox;   // theta is a contiguous input
        tr = thR[tp]; ti = thI[tp];
    }
    #pragma unroll
    for (int co = 0; co < COUT; co++) {
        long op = (long)b*COUT*CST + (long)co*CST + (long)oy*LD + ox;
        if (thR) {
            outR[op] = ar[co]*tr - ai[co]*ti;
            outI[op] = ar[co]*ti + ai[co]*tr;
        } else {
            outR[op] = ar[co];
            outI[op] = ai[co];
        }
    }
}

// ------------------- final reduction: sum r^2 and f^2 -------------------
__global__ void reduce_k(const float* __restrict__ f, const float* __restrict__ x)
{
    __shared__ float sr[256];
    __shared__ float sf[256];
    long t = blockIdx.x*256L + threadIdx.x;
    float rv = 0.f, fv = 0.f;
    if (t < (long)Bn*IMG2) {
        int b = (int)(t / IMG2);
        int p = (int)(t % IMG2);
        int i = p / IMG, j = p % IMG;
        fv = f[t];
        float Ax = 0.f;
        if (!(i==0 || i==IMG-1 || j==0 || j==IMG-1)) {
            long sb = (long)b*MP2 + (long)(i-1)*MP + (j-1);
            float sw = d_st[0L*Bn*MP2 + sb];
            float se = d_st[1L*Bn*MP2 + sb];
            float sn = d_st[2L*Bn*MP2 + sb];
            float ss = d_st[3L*Bn*MP2 + sb];
            float sc = d_st[4L*Bn*MP2 + sb];
            const float* xb = x + (long)b*IMG2;
            Ax = ss*xb[(i-1)*IMG + j] + sw*xb[i*IMG + j-1] + sc*xb[i*IMG + j]
               + se*xb[i*IMG + j+1] + sn*xb[(i+1)*IMG + j];
        }
        rv = fv - Ax;
    }
    sr[threadIdx.x] = rv*rv;
    sf[threadIdx.x] = fv*fv;
    __syncthreads();
    for (int s = 128; s > 0; s >>= 1) {
        if (threadIdx.x < s) { sr[threadIdx.x] += sr[threadIdx.x+s]; sf[threadIdx.x] += sf[threadIdx.x+s]; }
        __syncthreads();
    }
    if (threadIdx.x == 0) {
        atomicAdd(&d_acc[0], sr[0]);
        atomicAdd(&d_acc[1], sf[0]);
    }
}

__global__ void finalize_k(float* __restrict__ out)
{
    out[0] = sqrtf(d_acc[0] / d_acc[1]);
}

// ------------------- host side -------------------
extern "C" void kernel_launch(void* const* d_in, const int* in_sizes, int n_in,
                              void* d_out, int out_size)
{
    (void)in_sizes; (void)n_in; (void)out_size;
    const float* f    = (const float*)d_in[0];
    const float* coef = (const float*)d_in[1];
    const float* W[2][3][2] = {
        { { (const float*)d_in[2],  (const float*)d_in[3]  },
          { (const float*)d_in[4],  (const float*)d_in[5]  },
          { (const float*)d_in[6],  (const float*)d_in[7]  } },
        { { (const float*)d_in[10], (const float*)d_in[11] },
          { (const float*)d_in[12], (const float*)d_in[13] },
          { (const float*)d_in[14], (const float*)d_in[15] } }
    };
    const float* TH[2][2] = {
        { (const float*)d_in[8],  (const float*)d_in[9]  },
        { (const float*)d_in[16], (const float*)d_in[17] }
    };

    float *pSf,*pSfT,*pCb,*pSb,*pCbT,*pSbT,*pxA,*pxB,*pr1,*pT1,*pY;
    float *pbAr,*pbAi,*pbBr,*pbBi,*pZr,*pZi,*pP,*pQ,*pg1,*pg2;
    cudaGetSymbolAddress((void**)&pSf,  d_Sf);
    cudaGetSymbolAddress((void**)&pSfT, d_SfT);
    cudaGetSymbolAddress((void**)&pCb,  d_Cb);
    cudaGetSymbolAddress((void**)&pSb,  d_Sb);
    cudaGetSymbolAddress((void**)&pCbT, d_CbT);
    cudaGetSymbolAddress((void**)&pSbT, d_SbT);
    cudaGetSymbolAddress((void**)&pxA,  d_xA);
    cudaGetSymbolAddress((void**)&pxB,  d_xB);
    cudaGetSymbolAddress((void**)&pr1,  d_r1);
    cudaGetSymbolAddress((void**)&pT1,  d_T1);
    cudaGetSymbolAddress((void**)&pY,   d_Y);
    cudaGetSymbolAddress((void**)&pbAr, d_bAr);
    cudaGetSymbolAddress((void**)&pbAi, d_bAi);
    cudaGetSymbolAddress((void**)&pbBr, d_bBr);
    cudaGetSymbolAddress((void**)&pbBi, d_bBi);
    cudaGetSymbolAddress((void**)&pZr,  d_Zr);
    cudaGetSymbolAddress((void**)&pZi,  d_Zi);
    cudaGetSymbolAddress((void**)&pP,   d_P);
    cudaGetSymbolAddress((void**)&pQ,   d_Q);
    cudaGetSymbolAddress((void**)&pg1,  d_g1);
    cudaGetSymbolAddress((void**)&pg2,  d_g2);

    const int EW_IMG = (Bn*IMG2 + 255)/256;
    const int EW_MP  = (Bn*MP2  + 255)/256;
    const int EW_NP  = (NP*NP   + 255)/256;

    init_basis_k<<<EW_NP,256>>>();
    stencil_k<<<EW_MP,256>>>(coef);
    zero_k<<<EW_IMG,256>>>(pxA, (long)Bn*IMG2);

    // 10 smoothing sweeps, ping-pong; ends with x in d_xA
    {
        float* cur = pxA; float* nxt = pxB;
        for (int t = 0; t < 10; t++) {
            smooth_k<<<EW_IMG,256>>>(cur, nxt, f);
            float* tmp = cur; cur = nxt; nxt = tmp;
        }
    }
    resid1_k<<<EW_MP,256>>>(pxA, f);

    // forward: T1 = Sf * r1 ; Y = -(1/511^2) * T1 * Sf^T
    {
        dim3 g1((MP+63)/64, (NP+127)/128, Bn);
        gemmNN_k<<<g1,256>>>(pSf, 0, pr1, (long)MP*LD, pT1, (long)NP*LD,
                             NP, MP, MP, 1.0f);
        dim3 g2((NP+63)/64, (NP+127)/128, Bn);
        gemmNN_k<<<g2,256>>>(pT1, (long)NP*LD, pSfT, 0, pY, (long)NP*LD,
                             NP, NP, MP, -1.0f/(511.0f*511.0f));
    }

    dim3 cblk(32,8), cgrd((NP+31)/32, (NP+7)/8, Bn);
    for (int h = 0; h < 2; h++) {
        // forward conv chain: Y(1ch real) -> 4 -> 4 -> 1 (theta fused at layer 3)
        conv_k<1,4><<<cgrd,cblk>>>(pY, nullptr, pbAr, pbAi,
                                   W[h][0][0], W[h][0][1], 0, nullptr, nullptr);
        conv_k<4,4><<<cgrd,cblk>>>(pbAr, pbAi, pbBr, pbBi,
                                   W[h][1][0], W[h][1][1], 0, nullptr, nullptr);
        conv_k<4,1><<<cgrd,cblk>>>(pbBr, pbBi, pZr, pZi,
                                   W[h][2][0], W[h][2][1], 0, TH[h][0], TH[h][1]);
        // backward conj-transposed chain: 1 -> 4 -> 4 -> 1
        conv_k<1,4><<<cgrd,cblk>>>(pZr, pZi, pbBr, pbBi,
                                   W[h][2][0], W[h][2][1], 1, nullptr, nullptr);
        conv_k<4,4><<<cgrd,cblk>>>(pbBr, pbBi, pbAr, pbAi,
                                   W[h][1][0], W[h][1][1], 1, nullptr, nullptr);
        conv_k<4,1><<<cgrd,cblk>>>(pbAr, pbAi, pZr, pZi,
                                   W[h][0][0], W[h][0][1], 1, nullptr, nullptr);

        // fused inverse stage 1: P = Cb*Zr + Sb*Zi ; Q = Cb*Zi - Sb*Zr
        dim3 gpq((NP+63)/64, (MP+63)/64, Bn);
        gemmPQ_k<<<gpq,256>>>(pCb, pSb, pZr, pZi, (long)NP*LD,
                              pP, pQ, (long)MP*LD, MP, NP, NP);
        // fused inverse stage 2 + apply: x[int] += (P*CbT + Q*SbT) .* g
        dim3 ge((MP+63)/64, (MP+63)/64, Bn);
        gemmE_k<<<ge,256>>>(pP, pQ, (long)MP*LD, pCbT, pSbT,
                            h == 0 ? pg1 : pg2, pxA, MP, MP, NP);
    }

    reduce_k<<<EW_IMG,256>>>(f, pxA);
    finalize_k<<<1,1>>>((float*)d_out);
}